// round 1
// baseline (speedup 1.0000x reference)
#include <cuda_runtime.h>

#define BATCH 8
#define SEQ   2048
#define EMB   1024
#define HD    128

// scratch (allocation-free rule: __device__ globals)
__device__ float g_K[BATCH * SEQ * HD];
__device__ float g_V[BATCH * SEQ * HD];

// ---------------------------------------------------------------------------
// Projection: out[m][h] = sum_c x[m][c] * W[c][h]
// grid: (B*T/64, 2)  blockIdx.y selects (W_key -> g_K) or (W_value -> g_V)
// block: 256 threads, each computes a 4x8 micro-tile of a 64x128 block tile.
// ---------------------------------------------------------------------------
__global__ __launch_bounds__(256) void proj_kernel(
    const float* __restrict__ x,
    const float* __restrict__ Wk,
    const float* __restrict__ Wv)
{
    const float* W   = (blockIdx.y == 0) ? Wk : Wv;
    float*       dst = (blockIdx.y == 0) ? g_K : g_V;
    const int row0 = blockIdx.x * 64;

    __shared__ float xs[64 * 36];    // 64 rows x 32 cols, stride 36 (16B-aligned rows)
    __shared__ float ws[32 * 132];   // 32 rows x 128 cols, stride 132

    const int tid = threadIdx.x;
    const int tx  = tid & 15;        // 16 col-threads
    const int ty  = tid >> 4;        // 16 row-threads

    float acc[4][8];
#pragma unroll
    for (int i = 0; i < 4; i++)
#pragma unroll
        for (int j = 0; j < 8; j++) acc[i][j] = 0.0f;

    for (int kk = 0; kk < EMB; kk += 32) {
        // stage x tile: 64x32 = 512 float4, 2 per thread
#pragma unroll
        for (int q = 0; q < 2; q++) {
            int f  = q * 256 + tid;
            int r  = f >> 3;
            int c4 = f & 7;
            float4 v = *(const float4*)&x[(size_t)(row0 + r) * EMB + kk + c4 * 4];
            *(float4*)&xs[r * 36 + c4 * 4] = v;
        }
        // stage W tile: 32x128 = 1024 float4, 4 per thread
#pragma unroll
        for (int q = 0; q < 4; q++) {
            int f  = q * 256 + tid;
            int r  = f >> 5;
            int c4 = f & 31;
            float4 v = *(const float4*)&W[(size_t)(kk + r) * HD + c4 * 4];
            *(float4*)&ws[r * 132 + c4 * 4] = v;
        }
        __syncthreads();

#pragma unroll 8
        for (int k = 0; k < 32; k++) {
            float a[4];
#pragma unroll
            for (int i = 0; i < 4; i++) a[i] = xs[(ty * 4 + i) * 36 + k];
            float4 b0 = *(float4*)&ws[k * 132 + tx * 8];
            float4 b1 = *(float4*)&ws[k * 132 + tx * 8 + 4];
            float bb[8] = {b0.x, b0.y, b0.z, b0.w, b1.x, b1.y, b1.z, b1.w};
#pragma unroll
            for (int i = 0; i < 4; i++)
#pragma unroll
                for (int j = 0; j < 8; j++) acc[i][j] += a[i] * bb[j];
        }
        __syncthreads();
    }

#pragma unroll
    for (int i = 0; i < 4; i++) {
        size_t base = (size_t)(row0 + ty * 4 + i) * HD + tx * 8;
        *(float4*)&dst[base]     = make_float4(acc[i][0], acc[i][1], acc[i][2], acc[i][3]);
        *(float4*)&dst[base + 4] = make_float4(acc[i][4], acc[i][5], acc[i][6], acc[i][7]);
    }
}

// ---------------------------------------------------------------------------
// Flash attention, fp32, causal, q == k (source bug).
// grid: (T/64, B).  blockIdx.x reversed so longest blocks launch first.
// block: 256 threads. Tile: 64 q-rows x 64 kv-rows, HD=128.
// Thread (tx,ty) owns S rows ty*4..+4, S cols tx*4..+4, O cols tx*8..+8.
// ---------------------------------------------------------------------------
__global__ __launch_bounds__(256) void attn_kernel(float* __restrict__ out)
{
    extern __shared__ float sm[];
    float* Qs = sm;                   // 64 * 132
    float* Ks = Qs + 64 * 132;        // 64 * 132
    float* Vs = Ks + 64 * 132;        // 64 * 132
    float* Ps = Vs + 64 * 132;        // 64 * 68

    const int b  = blockIdx.y;
    const int qt = (gridDim.x - 1) - blockIdx.x;   // reverse for load balance
    const int tid = threadIdx.x;
    const int tx = tid & 15;
    const int ty = tid >> 4;
    const float scale = 0.08838834764831845f;      // 128^-0.5

    const float* Kb = g_K + (size_t)b * SEQ * HD;
    const float* Vb = g_V + (size_t)b * SEQ * HD;

    // load Q tile once (Q rows == K rows of this q-tile)
#pragma unroll
    for (int q = 0; q < 8; q++) {
        int f  = q * 256 + tid;
        int r  = f >> 5;
        int c4 = f & 31;
        *(float4*)&Qs[r * 132 + c4 * 4] =
            *(const float4*)&Kb[(size_t)(qt * 64 + r) * HD + c4 * 4];
    }

    float O[4][8];
#pragma unroll
    for (int i = 0; i < 4; i++)
#pragma unroll
        for (int j = 0; j < 8; j++) O[i][j] = 0.0f;
    float mrow[4] = {-1e30f, -1e30f, -1e30f, -1e30f};
    float lrow[4] = {0.f, 0.f, 0.f, 0.f};

    for (int j = 0; j <= qt; j++) {
        __syncthreads();   // previous PV done before K/V/P reuse
        // stage K and V tiles
#pragma unroll
        for (int q = 0; q < 8; q++) {
            int f  = q * 256 + tid;
            int r  = f >> 5;
            int c4 = f & 31;
            size_t g = (size_t)(j * 64 + r) * HD + c4 * 4;
            *(float4*)&Ks[r * 132 + c4 * 4] = *(const float4*)&Kb[g];
            *(float4*)&Vs[r * 132 + c4 * 4] = *(const float4*)&Vb[g];
        }
        __syncthreads();

        // S = Q K^T
        float s[4][4];
#pragma unroll
        for (int i = 0; i < 4; i++)
#pragma unroll
            for (int c = 0; c < 4; c++) s[i][c] = 0.0f;

#pragma unroll 8
        for (int k = 0; k < HD; k += 4) {
            float4 a[4], bb[4];
#pragma unroll
            for (int i = 0; i < 4; i++) a[i]  = *(float4*)&Qs[(ty * 4 + i) * 132 + k];
#pragma unroll
            for (int c = 0; c < 4; c++) bb[c] = *(float4*)&Ks[(tx * 4 + c) * 132 + k];
#pragma unroll
            for (int i = 0; i < 4; i++)
#pragma unroll
                for (int c = 0; c < 4; c++) {
                    s[i][c] += a[i].x * bb[c].x;
                    s[i][c] += a[i].y * bb[c].y;
                    s[i][c] += a[i].z * bb[c].z;
                    s[i][c] += a[i].w * bb[c].w;
                }
        }

        const bool diag = (j == qt);
#pragma unroll
        for (int i = 0; i < 4; i++)
#pragma unroll
            for (int c = 0; c < 4; c++) {
                float v = s[i][c] * scale;
                if (diag && (j * 64 + tx * 4 + c) > (qt * 64 + ty * 4 + i)) v = -1e30f;
                s[i][c] = v;
            }

        // online softmax update, row reductions across the 16 tx threads
#pragma unroll
        for (int i = 0; i < 4; i++) {
            float mloc = fmaxf(fmaxf(s[i][0], s[i][1]), fmaxf(s[i][2], s[i][3]));
#pragma unroll
            for (int o = 1; o < 16; o <<= 1)
                mloc = fmaxf(mloc, __shfl_xor_sync(0xffffffffu, mloc, o));
            float mn = fmaxf(mrow[i], mloc);
            float p0 = __expf(s[i][0] - mn);
            float p1 = __expf(s[i][1] - mn);
            float p2 = __expf(s[i][2] - mn);
            float p3 = __expf(s[i][3] - mn);
            float ls = p0 + p1 + p2 + p3;
#pragma unroll
            for (int o = 1; o < 16; o <<= 1)
                ls += __shfl_xor_sync(0xffffffffu, ls, o);
            float alpha = __expf(mrow[i] - mn);
            mrow[i] = mn;
            lrow[i] = lrow[i] * alpha + ls;
#pragma unroll
            for (int jj = 0; jj < 8; jj++) O[i][jj] *= alpha;
            *(float4*)&Ps[(ty * 4 + i) * 68 + tx * 4] = make_float4(p0, p1, p2, p3);
        }
        __syncthreads();

        // O += P @ V
#pragma unroll 4
        for (int k = 0; k < 64; k++) {
            float a[4];
#pragma unroll
            for (int i = 0; i < 4; i++) a[i] = Ps[(ty * 4 + i) * 68 + k];
            float4 b0 = *(float4*)&Vs[k * 132 + tx * 8];
            float4 b1 = *(float4*)&Vs[k * 132 + tx * 8 + 4];
            float bb[8] = {b0.x, b0.y, b0.z, b0.w, b1.x, b1.y, b1.z, b1.w};
#pragma unroll
            for (int i = 0; i < 4; i++)
#pragma unroll
                for (int jj = 0; jj < 8; jj++) O[i][jj] += a[i] * bb[jj];
        }
    }

    // epilogue: normalize and store
#pragma unroll
    for (int i = 0; i < 4; i++) {
        float inv = 1.0f / lrow[i];
        size_t base = (size_t)b * SEQ * HD + (size_t)(qt * 64 + ty * 4 + i) * HD + tx * 8;
        *(float4*)&out[base] = make_float4(O[i][0] * inv, O[i][1] * inv,
                                           O[i][2] * inv, O[i][3] * inv);
        *(float4*)&out[base + 4] = make_float4(O[i][4] * inv, O[i][5] * inv,
                                               O[i][6] * inv, O[i][7] * inv);
    }
}

// ---------------------------------------------------------------------------
extern "C" void kernel_launch(void* const* d_in, const int* in_sizes, int n_in,
                              void* d_out, int out_size)
{
    const float* x  = (const float*)d_in[0];
    const float* Wk = (const float*)d_in[1];
    // d_in[2] = W_query: intentionally unused (reference uses W_key for q too)
    const float* Wv = (const float*)d_in[3];
    float* out = (float*)d_out;

    const size_t smem = (size_t)(3 * 64 * 132 + 64 * 68) * sizeof(float);  // 118,784 B
    cudaFuncSetAttribute(attn_kernel, cudaFuncAttributeMaxDynamicSharedMemorySize,
                         (int)smem);

    proj_kernel<<<dim3(BATCH * SEQ / 64, 2), 256>>>(x, Wk, Wv);
    attn_kernel<<<dim3(SEQ / 64, BATCH), 256, smem>>>(out);
}

// round 4
// speedup vs baseline: 6.4884x; 6.4884x over previous
#include <cuda_runtime.h>
#include <cstdint>

#define BATCH 8
#define SEQ   2048
#define EMB   1024
#define HD    128

// ---------------- scratch (allocation-free rule) ----------------
__device__ float g_K[BATCH * SEQ * HD];             // K = x @ Wk
__device__ float g_V[BATCH * SEQ * HD];             // V = x @ Wv
__device__ float g_Wt[2 * HD * EMB];                // [Wk^T ; Wv^T]  [n=256][c=1024]
__device__ float g_Opart[4 * BATCH * SEQ * HD];     // per-chunk unnormalized O
__device__ float g_lpart[4 * BATCH * SEQ];          // per-chunk row sums

// Work items (per batch): (qt, ch). chunk ch covers kv64 tiles [8ch, min(8ch+8, 2qt+2)).
// Sorted big-first (28 full-8 chunks, then 6,4,2-tile partial chunks).
__constant__ unsigned char ITEM_QT[40] = {
    15,15,15,15, 14,14,14, 13,13,13, 12,12,12, 11,11,11,
    10,10, 9,9, 8,8, 7,7, 6, 5, 4, 3,
    14,10,6,2, 13,9,5,1, 12,8,4,0 };
__constant__ unsigned char ITEM_CH[40] = {
    0,1,2,3, 0,1,2, 0,1,2, 0,1,2, 0,1,2,
    0,1, 0,1, 0,1, 0,1, 0, 0, 0, 0,
    3,2,1,0, 3,2,1,0, 3,2,1,0 };

// ---------------- helpers ----------------
__device__ __forceinline__ void cp16(uint32_t s, const void* g) {
    asm volatile("cp.async.cg.shared.global [%0], [%1], 16;" :: "r"(s), "l"(g));
}
#define CP_COMMIT() asm volatile("cp.async.commit_group;" ::: "memory")
template <int N>
__device__ __forceinline__ void cp_wait() {
    asm volatile("cp.async.wait_group %0;" :: "n"(N) : "memory");
}
__device__ __forceinline__ uint32_t tf32(float f) {
    uint32_t r; asm("cvt.rna.tf32.f32 %0, %1;" : "=r"(r) : "f"(f)); return r;
}
__device__ __forceinline__ void mma8(float* d, const uint32_t* a, const uint32_t* b) {
    asm volatile("mma.sync.aligned.m16n8k8.row.col.f32.tf32.tf32.f32 "
        "{%0,%1,%2,%3}, {%4,%5,%6,%7}, {%8,%9}, {%0,%1,%2,%3};"
        : "+f"(d[0]), "+f"(d[1]), "+f"(d[2]), "+f"(d[3])
        : "r"(a[0]), "r"(a[1]), "r"(a[2]), "r"(a[3]), "r"(b[0]), "r"(b[1]));
}

// ---------------------------------------------------------------------------
// Kernel 0: transpose [Wk;Wv] -> g_Wt[256][1024]
// ---------------------------------------------------------------------------
__global__ void transpose_w(const float* __restrict__ Wk, const float* __restrict__ Wv) {
    __shared__ float t[32][33];
    const int n0 = blockIdx.x * 32;
    const int c0 = blockIdx.y * 32;
    const float* W = (blockIdx.x < 4) ? Wk : Wv;
    const int nb = (blockIdx.x & 3) * 32;
    for (int r = threadIdx.y; r < 32; r += 8)
        t[r][threadIdx.x] = W[(size_t)(c0 + r) * HD + nb + threadIdx.x];
    __syncthreads();
    for (int r = threadIdx.y; r < 32; r += 8)
        g_Wt[(size_t)(n0 + r) * EMB + c0 + threadIdx.x] = t[threadIdx.x][r];
}

// ---------------------------------------------------------------------------
// Kernel 1: projection.  C[256m x 128n] = x_tile @ W  (wsel: 0 -> g_K, 1 -> g_V)
// grid (64, 2), 256 threads (8 warps x 32 rows). kc=32, 3-stage cp.async.
// smem per stage: A [256][36] + B [128][36] floats.
// ---------------------------------------------------------------------------
#define PJ_STAGE (256 * 36 + 128 * 36)   // 13824 floats
#define PJ_SMEM  (3 * PJ_STAGE * 4)      // 165888 bytes

__global__ __launch_bounds__(256, 1) void proj_kernel(const float* __restrict__ x) {
    extern __shared__ float sm[];
    const int tid = threadIdx.x, w = tid >> 5, lane = tid & 31;
    const int gid = lane >> 2, tig = lane & 3;
    const int m0 = blockIdx.x * 256;
    const int wsel = blockIdx.y;
    float* dst = wsel ? g_V : g_K;

    float acc[2][16][4];
#pragma unroll
    for (int i = 0; i < 2; i++)
#pragma unroll
        for (int t = 0; t < 16; t++)
#pragma unroll
            for (int v = 0; v < 4; v++) acc[i][t][v] = 0.0f;

    auto issue = [&](int st, int c) {
        float* As = sm + st * PJ_STAGE;
        float* Bs = As + 256 * 36;
        // A: 256 rows x 32 floats = 2048 cp16 ops -> 8 per thread
#pragma unroll
        for (int q = 0; q < 8; q++) {
            int f = q * 256 + tid, r = f >> 3, seg = f & 7;
            cp16((uint32_t)__cvta_generic_to_shared(&As[r * 36 + seg * 4]),
                 &x[(size_t)(m0 + r) * EMB + c * 32 + seg * 4]);
        }
        // B: 128 rows x 32 floats = 1024 ops -> 4 per thread
#pragma unroll
        for (int q = 0; q < 4; q++) {
            int f = q * 256 + tid, r = f >> 3, seg = f & 7;
            cp16((uint32_t)__cvta_generic_to_shared(&Bs[r * 36 + seg * 4]),
                 &g_Wt[(size_t)(wsel * 128 + r) * EMB + c * 32 + seg * 4]);
        }
    };

    issue(0, 0); CP_COMMIT();
    issue(1, 1); CP_COMMIT();

    for (int c = 0; c < 32; c++) {
        if (c + 2 < 32) { issue((c + 2) % 3, c + 2); }
        CP_COMMIT();
        cp_wait<2>();
        __syncthreads();

        const float* As = sm + (c % 3) * PJ_STAGE;
        const float* Bs = As + 256 * 36;
#pragma unroll
        for (int s = 0; s < 4; s++) {
            const int k0 = 8 * s;
            uint32_t a[2][4];
#pragma unroll
            for (int i = 0; i < 2; i++) {
                int r = 32 * w + 16 * i + gid;
                a[i][0] = tf32(As[r * 36 + k0 + tig]);
                a[i][1] = tf32(As[(r + 8) * 36 + k0 + tig]);
                a[i][2] = tf32(As[r * 36 + k0 + tig + 4]);
                a[i][3] = tf32(As[(r + 8) * 36 + k0 + tig + 4]);
            }
#pragma unroll
            for (int t = 0; t < 16; t++) {
                uint32_t b[2];
                b[0] = tf32(Bs[(8 * t + gid) * 36 + k0 + tig]);
                b[1] = tf32(Bs[(8 * t + gid) * 36 + k0 + tig + 4]);
                mma8(acc[0][t], a[0], b);
                mma8(acc[1][t], a[1], b);
            }
        }
        __syncthreads();
    }

    // epilogue: write C
#pragma unroll
    for (int i = 0; i < 2; i++) {
        int r0 = m0 + 32 * w + 16 * i + gid;
#pragma unroll
        for (int t = 0; t < 16; t++) {
            int h = 8 * t + 2 * tig;
            *(float2*)&dst[(size_t)r0 * HD + h]       = make_float2(acc[i][t][0], acc[i][t][1]);
            *(float2*)&dst[(size_t)(r0 + 8) * HD + h] = make_float2(acc[i][t][2], acc[i][t][3]);
        }
    }
}

// ---------------------------------------------------------------------------
// Kernel 2: attention.  Item = (qt, ch): 128 q-rows, kv64 tiles jj in [8ch, jend).
// S (16x64 per warp) in regs -> exp/mask/rowsum in regs -> PV with C-as-A trick.
// smem: Q [128][132], K/V double-buffered [64][132] x2 each.
// ---------------------------------------------------------------------------
#define AQ  0
#define AK  16896                 // 128*132
#define AV  (16896 + 16896)       // + 2*64*132
#define AT_SMEM ((16896 * 3) * 4) // 202752 bytes

__global__ __launch_bounds__(256, 1) void attn_kernel(float* __restrict__ out) {
    extern __shared__ float sm[];
    const int tid = threadIdx.x, w = tid >> 5, lane = tid & 31;
    const int gid = lane >> 2, tig = lane & 3;
    const int b = blockIdx.y;
    const int qt = ITEM_QT[blockIdx.x];
    const int ch = ITEM_CH[blockIdx.x];
    const int jbeg = 8 * ch;
    const int jend = min(8 * ch + 8, 2 * qt + 2);
    const int nch = (2 * qt + 9) >> 3;        // ceil((2qt+2)/8)
    const float SCALE = 0.08838834764831845f;

    const float* Kb = g_K + (size_t)b * SEQ * HD;
    const float* Vb = g_V + (size_t)b * SEQ * HD;

    // Q tile (source bug: q = key(x), so read g_K) + first K/V tile, one group
    {
#pragma unroll
        for (int q = 0; q < 16; q++) {
            int f = q * 256 + tid, r = f >> 5, seg = f & 31;
            cp16((uint32_t)__cvta_generic_to_shared(&sm[AQ + r * 132 + seg * 4]),
                 &Kb[(size_t)(qt * 128 + r) * HD + seg * 4]);
        }
        int tok0 = jbeg * 64;
#pragma unroll
        for (int q = 0; q < 8; q++) {
            int f = q * 256 + tid, r = f >> 5, seg = f & 31;
            cp16((uint32_t)__cvta_generic_to_shared(&sm[AK + r * 132 + seg * 4]),
                 &Kb[(size_t)(tok0 + r) * HD + seg * 4]);
            cp16((uint32_t)__cvta_generic_to_shared(&sm[AV + r * 132 + seg * 4]),
                 &Vb[(size_t)(tok0 + r) * HD + seg * 4]);
        }
        CP_COMMIT();
    }

    float o[16][4];
#pragma unroll
    for (int t = 0; t < 16; t++)
#pragma unroll
        for (int v = 0; v < 4; v++) o[t][v] = 0.0f;
    float l0 = 0.0f, l1 = 0.0f;

    const int qr0 = qt * 128 + 16 * w;    // warp's first q row

    for (int jj = jbeg; jj < jend; jj++) {
        const int buf = (jj - jbeg) & 1;
        const int nbuf = buf ^ 1;
        if (jj + 1 < jend) {
            int tok0 = (jj + 1) * 64;
#pragma unroll
            for (int q = 0; q < 8; q++) {
                int f = q * 256 + tid, r = f >> 5, seg = f & 31;
                cp16((uint32_t)__cvta_generic_to_shared(&sm[AK + nbuf * 8448 + r * 132 + seg * 4]),
                     &Kb[(size_t)(tok0 + r) * HD + seg * 4]);
                cp16((uint32_t)__cvta_generic_to_shared(&sm[AV + nbuf * 8448 + r * 132 + seg * 4]),
                     &Vb[(size_t)(tok0 + r) * HD + seg * 4]);
            }
        }
        CP_COMMIT();
        cp_wait<1>();
        __syncthreads();

        const int kv0 = jj * 64;
        if (kv0 <= qr0 + 15) {   // else warp tile fully masked: skip compute
            const float* Qs = sm + AQ;
            const float* Ks = sm + AK + buf * 8448;
            const float* Vs = sm + AV + buf * 8448;

            // ---- S = Q K^T  (warp: 16 q-rows x 64 kv-cols) ----
            float s[8][4];
#pragma unroll
            for (int t = 0; t < 8; t++)
#pragma unroll
                for (int v = 0; v < 4; v++) s[t][v] = 0.0f;

#pragma unroll
            for (int ks = 0; ks < 16; ks++) {
                const int k0 = 8 * ks;
                uint32_t a[4];
                a[0] = tf32(Qs[(16 * w + gid) * 132 + k0 + tig]);
                a[1] = tf32(Qs[(16 * w + gid + 8) * 132 + k0 + tig]);
                a[2] = tf32(Qs[(16 * w + gid) * 132 + k0 + tig + 4]);
                a[3] = tf32(Qs[(16 * w + gid + 8) * 132 + k0 + tig + 4]);
#pragma unroll
                for (int t = 0; t < 8; t++) {
                    uint32_t bb[2];
                    bb[0] = tf32(Ks[(8 * t + gid) * 132 + k0 + tig]);
                    bb[1] = tf32(Ks[(8 * t + gid) * 132 + k0 + tig + 4]);
                    mma8(s[t], a, bb);
                }
            }

            // ---- P = exp(scale * S), causal mask, row sums ----
            const bool domask = (kv0 + 63 > qr0);
#pragma unroll
            for (int t = 0; t < 8; t++) {
                const int col = kv0 + 8 * t + 2 * tig;
                float p0 = __expf(s[t][0] * SCALE);
                float p1 = __expf(s[t][1] * SCALE);
                float p2 = __expf(s[t][2] * SCALE);
                float p3 = __expf(s[t][3] * SCALE);
                if (domask) {
                    const int r0 = qr0 + gid, r1 = r0 + 8;
                    if (col > r0)     p0 = 0.0f;
                    if (col + 1 > r0) p1 = 0.0f;
                    if (col > r1)     p2 = 0.0f;
                    if (col + 1 > r1) p3 = 0.0f;
                }
                l0 += p0 + p1;
                l1 += p2 + p3;
                s[t][0] = p0; s[t][1] = p1; s[t][2] = p2; s[t][3] = p3;
            }

            // ---- O += P V  (A = P accum regs, permuted; B rows 2tig, 2tig+1) ----
#pragma unroll
            for (int ks = 0; ks < 8; ks++) {
                uint32_t a[4];
                a[0] = tf32(s[ks][0]);   // row gid,   col 8ks+2tig
                a[1] = tf32(s[ks][2]);   // row gid+8, col 8ks+2tig
                a[2] = tf32(s[ks][1]);   // row gid,   col 8ks+2tig+1
                a[3] = tf32(s[ks][3]);   // row gid+8, col 8ks+2tig+1
#pragma unroll
                for (int t = 0; t < 16; t++) {
                    uint32_t bb[2];
                    bb[0] = tf32(Vs[(8 * ks + 2 * tig) * 132 + 8 * t + gid]);
                    bb[1] = tf32(Vs[(8 * ks + 2 * tig + 1) * 132 + 8 * t + gid]);
                    mma8(o[t], a, bb);
                }
            }
        }
        __syncthreads();
    }

    // quad-reduce row sums (lanes gid*4+tig share rows gid / gid+8)
#pragma unroll
    for (int off = 1; off < 4; off <<= 1) {
        l0 += __shfl_xor_sync(0xffffffffu, l0, off);
        l1 += __shfl_xor_sync(0xffffffffu, l1, off);
    }

    const int row0 = qt * 128 + 16 * w + gid;
    if (nch == 1) {
        const float i0 = 1.0f / l0, i1 = 1.0f / l1;
#pragma unroll
        for (int t = 0; t < 16; t++) {
            int h = 8 * t + 2 * tig;
            *(float2*)&out[((size_t)b * SEQ + row0) * HD + h] =
                make_float2(o[t][0] * i0, o[t][1] * i0);
            *(float2*)&out[((size_t)b * SEQ + row0 + 8) * HD + h] =
                make_float2(o[t][2] * i1, o[t][3] * i1);
        }
    } else {
        float* Op = g_Opart + (size_t)ch * BATCH * SEQ * HD;
#pragma unroll
        for (int t = 0; t < 16; t++) {
            int h = 8 * t + 2 * tig;
            *(float2*)&Op[((size_t)b * SEQ + row0) * HD + h]     = make_float2(o[t][0], o[t][1]);
            *(float2*)&Op[((size_t)b * SEQ + row0 + 8) * HD + h] = make_float2(o[t][2], o[t][3]);
        }
        if (tig == 0) {
            g_lpart[ch * BATCH * SEQ + b * SEQ + row0]     = l0;
            g_lpart[ch * BATCH * SEQ + b * SEQ + row0 + 8] = l1;
        }
    }
}

// ---------------------------------------------------------------------------
// Kernel 3: combine chunk partials for qt >= 4 (rows t >= 512).
// One float4 per thread: 8 b x 1536 t x 32 col4 = 393216 -> grid 1536 x 256.
// ---------------------------------------------------------------------------
__global__ __launch_bounds__(256) void combine_kernel(float* __restrict__ out) {
    int idx = blockIdx.x * 256 + threadIdx.x;
    int c4 = idx & 31, r = idx >> 5;
    int b = r / 1536, t = 512 + (r % 1536);
    int qt = t >> 7;
    int nch = (2 * qt + 9) >> 3;
    size_t row = (size_t)b * SEQ + t;

    float l = 0.0f;
    float4 o = make_float4(0.f, 0.f, 0.f, 0.f);
    for (int ch = 0; ch < nch; ch++) {
        l += g_lpart[ch * BATCH * SEQ + row];
        float4 v = *(const float4*)&g_Opart[(size_t)ch * BATCH * SEQ * HD + row * HD + c4 * 4];
        o.x += v.x; o.y += v.y; o.z += v.z; o.w += v.w;
    }
    float inv = 1.0f / l;
    *(float4*)&out[row * HD + c4 * 4] =
        make_float4(o.x * inv, o.y * inv, o.z * inv, o.w * inv);
}

// ---------------------------------------------------------------------------
extern "C" void kernel_launch(void* const* d_in, const int* in_sizes, int n_in,
                              void* d_out, int out_size)
{
    const float* x  = (const float*)d_in[0];
    const float* Wk = (const float*)d_in[1];
    // d_in[2] = W_query: intentionally unused (reference uses W_key for q too)
    const float* Wv = (const float*)d_in[3];
    float* out = (float*)d_out;

    cudaFuncSetAttribute(proj_kernel, cudaFuncAttributeMaxDynamicSharedMemorySize, PJ_SMEM);
    cudaFuncSetAttribute(attn_kernel, cudaFuncAttributeMaxDynamicSharedMemorySize, AT_SMEM);

    transpose_w<<<dim3(8, 32), dim3(32, 8)>>>(Wk, Wv);
    proj_kernel<<<dim3(64, 2), 256, PJ_SMEM>>>(x);
    attn_kernel<<<dim3(40, 8), 256, AT_SMEM>>>(out);
    combine_kernel<<<1536, 256>>>(out);
}

// round 5
// speedup vs baseline: 7.0241x; 1.0826x over previous
#include <cuda_runtime.h>
#include <cstdint>

#define BATCH 8
#define SEQ   2048
#define EMB   1024
#define HD    128

// ---------------- scratch (allocation-free rule) ----------------
__device__ float g_K [BATCH * SEQ * HD];        // K = x @ Wk, tf32-rounded, h PERMUTED
__device__ float g_Vt[BATCH * HD * SEQ];        // V^T [b][h][t], tf32-rounded, h natural
__device__ float g_Wt[2 * HD * EMB];            // [Wk^T ; Wv^T]  [n=256][c=1024]
__device__ float g_Opart[8 * BATCH * SEQ * HD]; // per-chunk unnormalized O
__device__ float g_lpart[8 * BATCH * SEQ];      // per-chunk row sums

// Work items (per batch): (qt, ch). chunk ch covers kv64 tiles [4ch, min(4ch+4, 2qt+2)).
// 64 full 4-tile chunks (qt desc) then 8 partial 2-tile chunks. nch(qt) = (qt+2)>>1.
__constant__ unsigned char ITEM_QT[72] = {
    15,15,15,15,15,15,15,15, 14,14,14,14,14,14,14, 13,13,13,13,13,13,13,
    12,12,12,12,12,12, 11,11,11,11,11,11, 10,10,10,10,10, 9,9,9,9,9,
    8,8,8,8, 7,7,7,7, 6,6,6, 5,5,5, 4,4, 3,3, 2, 1,
    14,12,10,8,6,4,2,0 };
__constant__ unsigned char ITEM_CH[72] = {
    0,1,2,3,4,5,6,7, 0,1,2,3,4,5,6, 0,1,2,3,4,5,6,
    0,1,2,3,4,5, 0,1,2,3,4,5, 0,1,2,3,4, 0,1,2,3,4,
    0,1,2,3, 0,1,2,3, 0,1,2, 0,1,2, 0,1, 0,1, 0, 0,
    7,6,5,4,3,2,1,0 };

// ---------------- helpers ----------------
__device__ __forceinline__ void cp16(uint32_t s, const void* g) {
    asm volatile("cp.async.cg.shared.global [%0], [%1], 16;" :: "r"(s), "l"(g));
}
#define CP_COMMIT() asm volatile("cp.async.commit_group;" ::: "memory")
template <int N>
__device__ __forceinline__ void cp_wait() {
    asm volatile("cp.async.wait_group %0;" :: "n"(N) : "memory");
}
__device__ __forceinline__ uint32_t tf32(float f) {
    uint32_t r; asm("cvt.rna.tf32.f32 %0, %1;" : "=r"(r) : "f"(f)); return r;
}
__device__ __forceinline__ void mma8(float* d, const uint32_t* a, uint32_t b0, uint32_t b1) {
    asm volatile("mma.sync.aligned.m16n8k8.row.col.f32.tf32.tf32.f32 "
        "{%0,%1,%2,%3}, {%4,%5,%6,%7}, {%8,%9}, {%0,%1,%2,%3};"
        : "+f"(d[0]), "+f"(d[1]), "+f"(d[2]), "+f"(d[3])
        : "r"(a[0]), "r"(a[1]), "r"(a[2]), "r"(a[3]), "r"(b0), "r"(b1));
}

// ---------------------------------------------------------------------------
// Kernel 0: transpose [Wk;Wv] -> g_Wt[256][1024]
// ---------------------------------------------------------------------------
__global__ void transpose_w(const float* __restrict__ Wk, const float* __restrict__ Wv) {
    __shared__ float t[32][33];
    const int n0 = blockIdx.x * 32;
    const int c0 = blockIdx.y * 32;
    const float* W = (blockIdx.x < 4) ? Wk : Wv;
    const int nb = (blockIdx.x & 3) * 32;
    for (int r = threadIdx.y; r < 32; r += 8)
        t[r][threadIdx.x] = W[(size_t)(c0 + r) * HD + nb + threadIdx.x];
    __syncthreads();
    for (int r = threadIdx.y; r < 32; r += 8)
        g_Wt[(size_t)(n0 + r) * EMB + c0 + threadIdx.x] = t[threadIdx.x][r];
}

// ---------------------------------------------------------------------------
// Kernel 1: projection.  C[256m x 128n] = x_tile @ W  (wsel: 0 -> g_K, 1 -> g_Vt)
// grid (64, 2), 256 threads (8 warps x 32 rows). kc=32, 3-stage cp.async.
// Epilogue stores tf32-ROUNDED values; g_K with permuted h; g_Vt transposed.
// ---------------------------------------------------------------------------
#define PJ_STAGE (256 * 36 + 128 * 36)   // 13824 floats
#define PJ_SMEM  (3 * PJ_STAGE * 4)      // 165888 bytes

__global__ __launch_bounds__(256, 1) void proj_kernel(const float* __restrict__ x) {
    extern __shared__ float sm[];
    const int tid = threadIdx.x, w = tid >> 5, lane = tid & 31;
    const int gid = lane >> 2, tig = lane & 3;
    const int m0 = blockIdx.x * 256;
    const int wsel = blockIdx.y;

    float acc[2][16][4];
#pragma unroll
    for (int i = 0; i < 2; i++)
#pragma unroll
        for (int t = 0; t < 16; t++)
#pragma unroll
            for (int v = 0; v < 4; v++) acc[i][t][v] = 0.0f;

    auto issue = [&](int st, int c) {
        float* As = sm + st * PJ_STAGE;
        float* Bs = As + 256 * 36;
#pragma unroll
        for (int q = 0; q < 8; q++) {
            int f = q * 256 + tid, r = f >> 3, seg = f & 7;
            cp16((uint32_t)__cvta_generic_to_shared(&As[r * 36 + seg * 4]),
                 &x[(size_t)(m0 + r) * EMB + c * 32 + seg * 4]);
        }
#pragma unroll
        for (int q = 0; q < 4; q++) {
            int f = q * 256 + tid, r = f >> 3, seg = f & 7;
            cp16((uint32_t)__cvta_generic_to_shared(&Bs[r * 36 + seg * 4]),
                 &g_Wt[(size_t)(wsel * 128 + r) * EMB + c * 32 + seg * 4]);
        }
    };

    issue(0, 0); CP_COMMIT();
    issue(1, 1); CP_COMMIT();

    for (int c = 0; c < 32; c++) {
        if (c + 2 < 32) { issue((c + 2) % 3, c + 2); }
        CP_COMMIT();
        cp_wait<2>();
        __syncthreads();

        const float* As = sm + (c % 3) * PJ_STAGE;
        const float* Bs = As + 256 * 36;
#pragma unroll
        for (int s = 0; s < 4; s++) {
            const int k0 = 8 * s;
            uint32_t a[2][4];
#pragma unroll
            for (int i = 0; i < 2; i++) {
                int r = 32 * w + 16 * i + gid;
                a[i][0] = tf32(As[r * 36 + k0 + tig]);
                a[i][1] = tf32(As[(r + 8) * 36 + k0 + tig]);
                a[i][2] = tf32(As[r * 36 + k0 + tig + 4]);
                a[i][3] = tf32(As[(r + 8) * 36 + k0 + tig + 4]);
            }
#pragma unroll
            for (int t = 0; t < 16; t++) {
                uint32_t b0 = tf32(Bs[(8 * t + gid) * 36 + k0 + tig]);
                uint32_t b1 = tf32(Bs[(8 * t + gid) * 36 + k0 + tig + 4]);
                mma8(acc[0][t], a[0], b0, b1);
                mma8(acc[1][t], a[1], b0, b1);
            }
        }
        __syncthreads();
    }

    // epilogue: tf32-round, then store
    if (wsel == 0) {
        // g_K with permuted h within each 8-group: col c -> (c<4 ? 2c : 2(c-4)+1)
        const int c0 = 2 * tig, c1 = 2 * tig + 1;
        const int p0 = (c0 < 4) ? 2 * c0 : 2 * (c0 - 4) + 1;
        const int p1 = (c1 < 4) ? 2 * c1 : 2 * (c1 - 4) + 1;
#pragma unroll
        for (int i = 0; i < 2; i++) {
            int r0 = m0 + 32 * w + 16 * i + gid;
#pragma unroll
            for (int t = 0; t < 16; t++) {
                g_K[(size_t)r0 * HD + 8 * t + p0]       = __uint_as_float(tf32(acc[i][t][0]));
                g_K[(size_t)r0 * HD + 8 * t + p1]       = __uint_as_float(tf32(acc[i][t][1]));
                g_K[(size_t)(r0 + 8) * HD + 8 * t + p0] = __uint_as_float(tf32(acc[i][t][2]));
                g_K[(size_t)(r0 + 8) * HD + 8 * t + p1] = __uint_as_float(tf32(acc[i][t][3]));
            }
        }
    } else {
        // g_Vt[b][h][t], natural h. Lanes gid -> consecutive tokens: full sectors.
        const int bb = m0 >> 11;
        const int tb = m0 & 2047;
        float* base = g_Vt + (size_t)bb * HD * SEQ;
#pragma unroll
        for (int i = 0; i < 2; i++) {
            int rl = 32 * w + 16 * i + gid;
#pragma unroll
            for (int t = 0; t < 16; t++) {
                int h0 = 8 * t + 2 * tig;
                base[(size_t)h0 * SEQ + tb + rl]           = __uint_as_float(tf32(acc[i][t][0]));
                base[(size_t)(h0 + 1) * SEQ + tb + rl]     = __uint_as_float(tf32(acc[i][t][1]));
                base[(size_t)h0 * SEQ + tb + rl + 8]       = __uint_as_float(tf32(acc[i][t][2]));
                base[(size_t)(h0 + 1) * SEQ + tb + rl + 8] = __uint_as_float(tf32(acc[i][t][3]));
            }
        }
    }
}

// ---------------------------------------------------------------------------
// Kernel 2: attention. Item = (qt, ch): 128 q-rows, kv64 tiles jj in [4ch, jend).
// Q frags preloaded to regs from gmem (already tf32 bits, permuted h).
// K tile [kv64][h128perm] stride 136; V tile [h128][kv64] stride 72; both dbl-buf.
// All fragment LDS are 64-bit, conflict-free. Only P needs cvt.
// ---------------------------------------------------------------------------
#define KSTR 136
#define VSTR 72
#define KBUF 8704            // 64*136 floats
#define VBASE 17408          // 2*KBUF
#define VBUF 9216            // 128*72 floats
#define AT_SMEM ((VBASE + 2 * VBUF) * 4)   // 143360 bytes

__global__ __launch_bounds__(256, 1) void attn_kernel(float* __restrict__ out) {
    extern __shared__ float sm[];
    const int tid = threadIdx.x, w = tid >> 5, lane = tid & 31;
    const int gid = lane >> 2, tig = lane & 3;
    const int b = blockIdx.y;
    const int qt = ITEM_QT[blockIdx.x];
    const int ch = ITEM_CH[blockIdx.x];
    const int jbeg = 4 * ch;
    const int jend = min(4 * ch + 4, 2 * qt + 2);
    const int nch = (qt + 2) >> 1;
    const float SCALE = 0.08838834764831845f;

    const float* Kb  = g_K  + (size_t)b * SEQ * HD;
    const float* Vtb = g_Vt + (size_t)b * HD * SEQ;

    auto stage = [&](int jj, int bsel) {
        const int tok0 = jj * 64;
        float* Ks = sm + bsel * KBUF;
        float* Vs = sm + VBASE + bsel * VBUF;
#pragma unroll
        for (int q = 0; q < 8; q++) {
            int f = q * 256 + tid, r = f >> 5, seg = f & 31;
            cp16((uint32_t)__cvta_generic_to_shared(&Ks[r * KSTR + seg * 4]),
                 &Kb[(size_t)(tok0 + r) * HD + seg * 4]);
        }
#pragma unroll
        for (int q = 0; q < 8; q++) {
            int f = q * 256 + tid, r = f >> 4, seg = f & 15;
            cp16((uint32_t)__cvta_generic_to_shared(&Vs[r * VSTR + seg * 4]),
                 &Vtb[(size_t)r * SEQ + tok0 + seg * 4]);
        }
    };

    stage(jbeg, 0); CP_COMMIT();

    // Q fragments direct from gmem (q = key(x) source bug: read g_K), once per item
    const int qrow = qt * 128 + 16 * w + gid;
    const uint2* Qg0 = (const uint2*)(Kb + (size_t)qrow * HD);
    const uint2* Qg8 = (const uint2*)(Kb + (size_t)(qrow + 8) * HD);
    uint32_t qa[16][4];
#pragma unroll
    for (int ks = 0; ks < 16; ks++) {
        uint2 u0 = Qg0[4 * ks + tig];
        uint2 u1 = Qg8[4 * ks + tig];
        qa[ks][0] = u0.x; qa[ks][2] = u0.y;   // rows gid:   cols tig, tig+4
        qa[ks][1] = u1.x; qa[ks][3] = u1.y;   // rows gid+8
    }

    float o[16][4];
#pragma unroll
    for (int t = 0; t < 16; t++)
#pragma unroll
        for (int v = 0; v < 4; v++) o[t][v] = 0.0f;
    float l0 = 0.0f, l1 = 0.0f;

    const int qr0 = qt * 128 + 16 * w;

    for (int jj = jbeg; jj < jend; jj++) {
        const int buf = (jj - jbeg) & 1;
        if (jj + 1 < jend) stage(jj + 1, buf ^ 1);
        CP_COMMIT();
        cp_wait<1>();
        __syncthreads();

        const int kv0 = jj * 64;
        if (kv0 <= qr0 + 15) {
            const float* Ks = sm + buf * KBUF;
            const float* Vs = sm + VBASE + buf * VBUF;

            // ---- S = Q K^T ----
            float s[8][4];
#pragma unroll
            for (int t = 0; t < 8; t++)
#pragma unroll
                for (int v = 0; v < 4; v++) s[t][v] = 0.0f;

#pragma unroll
            for (int ks = 0; ks < 16; ks++) {
#pragma unroll
                for (int t = 0; t < 8; t++) {
                    uint2 bb = *(const uint2*)(Ks + (8 * t + gid) * KSTR + 8 * ks + 2 * tig);
                    mma8(s[t], qa[ks], bb.x, bb.y);
                }
            }

            // ---- P = exp(scale*S), causal mask, row sums ----
            const bool domask = (kv0 + 63 > qr0);
#pragma unroll
            for (int t = 0; t < 8; t++) {
                const int col = kv0 + 8 * t + 2 * tig;
                float p0 = __expf(s[t][0] * SCALE);
                float p1 = __expf(s[t][1] * SCALE);
                float p2 = __expf(s[t][2] * SCALE);
                float p3 = __expf(s[t][3] * SCALE);
                if (domask) {
                    const int r0 = qr0 + gid, r1 = r0 + 8;
                    if (col > r0)     p0 = 0.0f;
                    if (col + 1 > r0) p1 = 0.0f;
                    if (col > r1)     p2 = 0.0f;
                    if (col + 1 > r1) p3 = 0.0f;
                }
                l0 += p0 + p1;
                l1 += p2 + p3;
                s[t][0] = p0; s[t][1] = p1; s[t][2] = p2; s[t][3] = p3;
            }

            // ---- O += P V (C-as-A permuted; V rows 2tig, 2tig+1 adjacent) ----
#pragma unroll
            for (int ks = 0; ks < 8; ks++) {
                uint32_t a[4];
                a[0] = tf32(s[ks][0]);
                a[1] = tf32(s[ks][2]);
                a[2] = tf32(s[ks][1]);
                a[3] = tf32(s[ks][3]);
#pragma unroll
                for (int t = 0; t < 16; t++) {
                    uint2 bb = *(const uint2*)(Vs + (8 * t + gid) * VSTR + 8 * ks + 2 * tig);
                    mma8(o[t], a, bb.x, bb.y);
                }
            }
        }
        __syncthreads();
    }

    // quad-reduce row sums
#pragma unroll
    for (int off = 1; off < 4; off <<= 1) {
        l0 += __shfl_xor_sync(0xffffffffu, l0, off);
        l1 += __shfl_xor_sync(0xffffffffu, l1, off);
    }

    const int row0 = qt * 128 + 16 * w + gid;
    if (nch == 1) {
        const float i0 = 1.0f / l0, i1 = 1.0f / l1;
#pragma unroll
        for (int t = 0; t < 16; t++) {
            int h = 8 * t + 2 * tig;
            *(float2*)&out[((size_t)b * SEQ + row0) * HD + h] =
                make_float2(o[t][0] * i0, o[t][1] * i0);
            *(float2*)&out[((size_t)b * SEQ + row0 + 8) * HD + h] =
                make_float2(o[t][2] * i1, o[t][3] * i1);
        }
    } else {
        float* Op = g_Opart + (size_t)ch * BATCH * SEQ * HD;
#pragma unroll
        for (int t = 0; t < 16; t++) {
            int h = 8 * t + 2 * tig;
            *(float2*)&Op[((size_t)b * SEQ + row0) * HD + h]     = make_float2(o[t][0], o[t][1]);
            *(float2*)&Op[((size_t)b * SEQ + row0 + 8) * HD + h] = make_float2(o[t][2], o[t][3]);
        }
        if (tig == 0) {
            g_lpart[ch * BATCH * SEQ + b * SEQ + row0]     = l0;
            g_lpart[ch * BATCH * SEQ + b * SEQ + row0 + 8] = l1;
        }
    }
}

// ---------------------------------------------------------------------------
// Kernel 3: combine chunk partials for qt >= 2 (rows t >= 256).
// 8 b x 1792 t x 32 col4 = 458752 threads -> 1792 blocks.
// ---------------------------------------------------------------------------
__global__ __launch_bounds__(256) void combine_kernel(float* __restrict__ out) {
    int idx = blockIdx.x * 256 + threadIdx.x;
    int c4 = idx & 31, r = idx >> 5;
    int b = r / 1792, t = 256 + (r % 1792);
    int qt = t >> 7;
    int nch = (qt + 2) >> 1;
    size_t row = (size_t)b * SEQ + t;

    float l = 0.0f;
    float4 o = make_float4(0.f, 0.f, 0.f, 0.f);
    for (int ch = 0; ch < nch; ch++) {
        l += g_lpart[ch * BATCH * SEQ + row];
        float4 v = *(const float4*)&g_Opart[(size_t)ch * BATCH * SEQ * HD + row * HD + c4 * 4];
        o.x += v.x; o.y += v.y; o.z += v.z; o.w += v.w;
    }
    float inv = 1.0f / l;
    *(float4*)&out[row * HD + c4 * 4] =
        make_float4(o.x * inv, o.y * inv, o.z * inv, o.w * inv);
}

// ---------------------------------------------------------------------------
extern "C" void kernel_launch(void* const* d_in, const int* in_sizes, int n_in,
                              void* d_out, int out_size)
{
    const float* x  = (const float*)d_in[0];
    const float* Wk = (const float*)d_in[1];
    // d_in[2] = W_query: intentionally unused (reference uses W_key for q too)
    const float* Wv = (const float*)d_in[3];
    float* out = (float*)d_out;

    cudaFuncSetAttribute(proj_kernel, cudaFuncAttributeMaxDynamicSharedMemorySize, PJ_SMEM);
    cudaFuncSetAttribute(attn_kernel, cudaFuncAttributeMaxDynamicSharedMemorySize, AT_SMEM);

    transpose_w<<<dim3(8, 32), dim3(32, 8)>>>(Wk, Wv);
    proj_kernel<<<dim3(64, 2), 256, PJ_SMEM>>>(x);
    attn_kernel<<<dim3(72, 8), 256, AT_SMEM>>>(out);
    combine_kernel<<<1792, 256>>>(out);
}

// round 6
// speedup vs baseline: 8.9537x; 1.2747x over previous
#include <cuda_runtime.h>
#include <cuda_fp16.h>
#include <cstdint>

#define BATCH 8
#define SEQ   2048
#define EMB   1024
#define HD    128

// ---------------- scratch (allocation-free rule) ----------------
__device__ __half g_Kh [BATCH * SEQ * HD];       // K = x@Wk, fp16, h interleaved-16
__device__ __half g_Vth[BATCH * HD * SEQ];       // V^T [b][h][t], fp16, t interleaved-16
__device__ __half g_Wh [2 * HD * EMB];           // [Wk^T;Wv^T] [n=256][c=1024], c interleaved-16
__device__ float  g_Opart[8 * BATCH * SEQ * HD]; // per-chunk unnormalized O
__device__ float  g_lpart[8 * BATCH * SEQ];      // per-chunk row sums
__device__ int    g_cnt[BATCH * 16];             // per (b, qt) finished-chunk counters

// Work items (per batch): (qt, ch). chunk ch covers kv64 tiles [4ch, min(4ch+4, 2qt+2)).
__constant__ unsigned char ITEM_QT[72] = {
    15,15,15,15,15,15,15,15, 14,14,14,14,14,14,14, 13,13,13,13,13,13,13,
    12,12,12,12,12,12, 11,11,11,11,11,11, 10,10,10,10,10, 9,9,9,9,9,
    8,8,8,8, 7,7,7,7, 6,6,6, 5,5,5, 4,4, 3,3, 2, 1,
    14,12,10,8,6,4,2,0 };
__constant__ unsigned char ITEM_CH[72] = {
    0,1,2,3,4,5,6,7, 0,1,2,3,4,5,6, 0,1,2,3,4,5,6,
    0,1,2,3,4,5, 0,1,2,3,4,5, 0,1,2,3,4, 0,1,2,3,4,
    0,1,2,3, 0,1,2,3, 0,1,2, 0,1,2, 0,1, 0,1, 0, 0,
    7,6,5,4,3,2,1,0 };

// ---------------- helpers ----------------
__device__ __forceinline__ void cp16(uint32_t s, const void* g) {
    asm volatile("cp.async.cg.shared.global [%0], [%1], 16;" :: "r"(s), "l"(g));
}
#define CP_COMMIT() asm volatile("cp.async.commit_group;" ::: "memory")
template <int N>
__device__ __forceinline__ void cp_wait() {
    asm volatile("cp.async.wait_group %0;" :: "n"(N) : "memory");
}
// pack two f32 -> f16x2 (lo = first arg)
__device__ __forceinline__ uint32_t packh2(float lo, float hi) {
    uint32_t d;
    asm("cvt.rn.f16x2.f32 %0, %1, %2;" : "=r"(d) : "f"(hi), "f"(lo));
    return d;
}
__device__ __forceinline__ void mma16(float* d, const uint32_t* a, uint32_t b0, uint32_t b1) {
    asm volatile("mma.sync.aligned.m16n8k16.row.col.f32.f16.f16.f32 "
        "{%0,%1,%2,%3}, {%4,%5,%6,%7}, {%8,%9}, {%0,%1,%2,%3};"
        : "+f"(d[0]), "+f"(d[1]), "+f"(d[2]), "+f"(d[3])
        : "r"(a[0]), "r"(a[1]), "r"(a[2]), "r"(a[3]), "r"(b0), "r"(b1));
}
// position of logical col c (0..15) in interleaved order [0,1,8,9,2,3,10,11,4,5,12,13,6,7,14,15]
__device__ __forceinline__ int pos16(int c) {
    return 4 * ((c & 7) >> 1) + 2 * ((c >> 3) & 1) + (c & 1);
}

// ---------------------------------------------------------------------------
// Kernel 0: W -> g_Wh (half, transposed, c interleaved-16). Also zero g_cnt.
// ---------------------------------------------------------------------------
__global__ void transpose_w(const float* __restrict__ Wk, const float* __restrict__ Wv) {
    __shared__ float t[32][33];
    if (blockIdx.x == 0 && blockIdx.y == 0) {
        int f = threadIdx.y * 32 + threadIdx.x;
        if (f < BATCH * 16) g_cnt[f] = 0;
    }
    const int n0 = blockIdx.x * 32;
    const int c0 = blockIdx.y * 32;
    const float* W = (blockIdx.x < 4) ? Wk : Wv;
    const int nb = (blockIdx.x & 3) * 32;
    for (int r = threadIdx.y; r < 32; r += 8)
        t[r][threadIdx.x] = W[(size_t)(c0 + r) * HD + nb + threadIdx.x];
    __syncthreads();
    for (int r = threadIdx.y; r < 32; r += 8) {
        int c = c0 + threadIdx.x;
        int cs = (c & ~15) + pos16(c & 15);
        g_Wh[(size_t)(n0 + r) * EMB + cs] = __float2half(t[threadIdx.x][r]);
    }
}

// ---------------------------------------------------------------------------
// Kernel 1: projection.  C[256m x 128n] = x_tile @ W  (wsel: 0 -> g_Kh, 1 -> g_Vth)
// grid (64, 2), 256 threads (8 warps). kc=32 (2 k16 steps), 3-stage cp.async.
// A tile f32 [256][40fl pad] (160B rows); B tile half [128][80h pad] (160B rows).
// ---------------------------------------------------------------------------
#define PJ_AB   40960                       // A tile bytes
#define PJ_ST   (40960 + 20480)             // stage bytes
#define PJ_SMEM (3 * PJ_ST)                 // 184320 bytes

__global__ __launch_bounds__(256, 1) void proj_kernel(const float* __restrict__ x) {
    extern __shared__ char smc[];
    const int tid = threadIdx.x, w = tid >> 5, lane = tid & 31;
    const int gid = lane >> 2, tig = lane & 3;
    const int m0 = blockIdx.x * 256;
    const int wsel = blockIdx.y;

    float acc[2][16][4];
#pragma unroll
    for (int i = 0; i < 2; i++)
#pragma unroll
        for (int t = 0; t < 16; t++)
#pragma unroll
            for (int v = 0; v < 4; v++) acc[i][t][v] = 0.0f;

    auto issue = [&](int st, int c) {
        char* As = smc + st * PJ_ST;
        char* Bs = As + PJ_AB;
#pragma unroll
        for (int q = 0; q < 8; q++) {     // A: 256 rows x 128B
            int f = q * 256 + tid, r = f >> 3, seg = f & 7;
            cp16((uint32_t)__cvta_generic_to_shared(As + r * 160 + seg * 16),
                 &x[(size_t)(m0 + r) * EMB + c * 32 + seg * 4]);
        }
#pragma unroll
        for (int q = 0; q < 2; q++) {     // B: 128 rows x 64B (halves)
            int f = q * 256 + tid, r = f >> 2, seg = f & 3;
            cp16((uint32_t)__cvta_generic_to_shared(Bs + r * 160 + seg * 16),
                 &g_Wh[(size_t)(wsel * 128 + r) * EMB + c * 32 + seg * 8]);
        }
    };

    issue(0, 0); CP_COMMIT();
    issue(1, 1); CP_COMMIT();

    for (int c = 0; c < 32; c++) {
        if (c + 2 < 32) { issue((c + 2) % 3, c + 2); }
        CP_COMMIT();
        cp_wait<2>();
        __syncthreads();

        const float* As = (const float*)(smc + (c % 3) * PJ_ST);
        const __half* Bs = (const __half*)(smc + (c % 3) * PJ_ST + PJ_AB);
#pragma unroll
        for (int ks = 0; ks < 2; ks++) {
            uint32_t a[2][4];
#pragma unroll
            for (int i = 0; i < 2; i++) {
                int r = 32 * w + 16 * i + gid;
                float2 lo0 = *(const float2*)(As + r * 40 + 16 * ks + 2 * tig);
                float2 lo1 = *(const float2*)(As + (r + 8) * 40 + 16 * ks + 2 * tig);
                float2 hi0 = *(const float2*)(As + r * 40 + 16 * ks + 2 * tig + 8);
                float2 hi1 = *(const float2*)(As + (r + 8) * 40 + 16 * ks + 2 * tig + 8);
                a[i][0] = packh2(lo0.x, lo0.y);
                a[i][1] = packh2(lo1.x, lo1.y);
                a[i][2] = packh2(hi0.x, hi0.y);
                a[i][3] = packh2(hi1.x, hi1.y);
            }
#pragma unroll
            for (int t = 0; t < 16; t++) {
                uint2 bb = *(const uint2*)(Bs + (8 * t + gid) * 80 + 16 * ks + 4 * tig);
                mma16(acc[0][t], a[0], bb.x, bb.y);
                mma16(acc[1][t], a[1], bb.x, bb.y);
            }
        }
        __syncthreads();
    }

    if (wsel == 0) {
        // g_Kh: store half2, h interleaved-16: hst = 16*(t>>1) + 4*tig + 2*(t&1)
#pragma unroll
        for (int i = 0; i < 2; i++) {
            int r0 = m0 + 32 * w + 16 * i + gid;
#pragma unroll
            for (int t = 0; t < 16; t++) {
                int hst = 16 * (t >> 1) + 4 * tig + 2 * (t & 1);
                *(__half2*)&g_Kh[(size_t)r0 * HD + hst] =
                    __floats2half2_rn(acc[i][t][0], acc[i][t][1]);
                *(__half2*)&g_Kh[(size_t)(r0 + 8) * HD + hst] =
                    __floats2half2_rn(acc[i][t][2], acc[i][t][3]);
            }
        }
    } else {
        // V^T: stage in smem [h=128][t=256 pad 264], then coalesced STG.
        __half* vs = (__half*)smc;
        const int VS = 264;
#pragma unroll
        for (int i = 0; i < 2; i++) {
            int tl = 32 * w + 16 * i + gid;                 // local token (0..255)
            int ts0 = (tl & ~15) + pos16(gid);
            int ts1 = ts0 + 2;                               // pos16(gid+8) = pos16(gid)+2
#pragma unroll
            for (int t = 0; t < 16; t++) {
                int h0 = 8 * t + 2 * tig;
                vs[h0 * VS + ts0]       = __float2half(acc[i][t][0]);
                vs[(h0 + 1) * VS + ts0] = __float2half(acc[i][t][1]);
                vs[h0 * VS + ts1]       = __float2half(acc[i][t][2]);
                vs[(h0 + 1) * VS + ts1] = __float2half(acc[i][t][3]);
            }
        }
        __syncthreads();
        const int bb = m0 >> 11;
        const int tb = m0 & 2047;
        __half* dst = g_Vth + (size_t)bb * HD * SEQ;
        int r = tid >> 1, half128 = (tid & 1) * 128;
#pragma unroll
        for (int k = 0; k < 16; k++) {
            uint4 v = *(uint4*)&vs[r * VS + half128 + k * 8];
            *(uint4*)&dst[(size_t)r * SEQ + tb + half128 + k * 8] = v;
        }
    }
}

// ---------------------------------------------------------------------------
// Kernel 2: attention + fused combine.
// Item = (qt, ch): 128 q-rows, kv64 tiles jj in [4ch, jend). fp16 m16n8k16.
// K tile [kv64][128h] stride 144h; V tile [h128][kv64] stride 80h; double-buffered.
// ---------------------------------------------------------------------------
#define KT0 0
#define KT1 9216                   // 64*144 halves
#define VT0 18432
#define VT1 28672                  // +128*80
#define AT_SMEM (38912 * 2)        // 77824 bytes

__global__ __launch_bounds__(256, 1) void attn_kernel(float* __restrict__ out) {
    extern __shared__ __half smh[];
    const int tid = threadIdx.x, w = tid >> 5, lane = tid & 31;
    const int gid = lane >> 2, tig = lane & 3;
    const int b = blockIdx.y;
    const int qt = ITEM_QT[blockIdx.x];
    const int ch = ITEM_CH[blockIdx.x];
    const int jbeg = 4 * ch;
    const int jend = min(4 * ch + 4, 2 * qt + 2);
    const int nch = (qt + 2) >> 1;
    const float SCALE = 0.08838834764831845f;

    const __half* Kbh  = g_Kh  + (size_t)b * SEQ * HD;
    const __half* Vtbh = g_Vth + (size_t)b * HD * SEQ;

    const int KOFF[2] = {KT0, KT1};
    const int VOFF[2] = {VT0, VT1};

    auto stage = [&](int jj, int bsel) {
        const int tok0 = jj * 64;
        __half* Ks = smh + KOFF[bsel];
        __half* Vs = smh + VOFF[bsel];
#pragma unroll
        for (int q = 0; q < 4; q++) {          // K: 64 rows x 256B
            int f = q * 256 + tid, r = f >> 4, seg = f & 15;
            cp16((uint32_t)__cvta_generic_to_shared(Ks + r * 144 + seg * 8),
                 &Kbh[(size_t)(tok0 + r) * HD + seg * 8]);
        }
#pragma unroll
        for (int q = 0; q < 4; q++) {          // V: 128 rows x 128B
            int f = q * 256 + tid, r = f >> 3, seg = f & 7;
            cp16((uint32_t)__cvta_generic_to_shared(Vs + r * 80 + seg * 8),
                 &Vtbh[(size_t)r * SEQ + tok0 + seg * 8]);
        }
    };

    stage(jbeg, 0); CP_COMMIT();

    // Q fragments from gmem (q = key(x) source bug: read g_Kh), once per item
    const int qrow = qt * 128 + 16 * w + gid;
    const uint2* Qg0 = (const uint2*)(Kbh + (size_t)qrow * HD);
    const uint2* Qg8 = (const uint2*)(Kbh + (size_t)(qrow + 8) * HD);
    uint32_t qa[8][4];
#pragma unroll
    for (int ks = 0; ks < 8; ks++) {
        uint2 u0 = Qg0[4 * ks + tig];
        uint2 u1 = Qg8[4 * ks + tig];
        qa[ks][0] = u0.x; qa[ks][2] = u0.y;
        qa[ks][1] = u1.x; qa[ks][3] = u1.y;
    }

    float o[16][4];
#pragma unroll
    for (int t = 0; t < 16; t++)
#pragma unroll
        for (int v = 0; v < 4; v++) o[t][v] = 0.0f;
    float l0 = 0.0f, l1 = 0.0f;

    const int qr0 = qt * 128 + 16 * w;

    for (int jj = jbeg; jj < jend; jj++) {
        const int buf = (jj - jbeg) & 1;
        if (jj + 1 < jend) stage(jj + 1, buf ^ 1);
        CP_COMMIT();
        cp_wait<1>();
        __syncthreads();

        const int kv0 = jj * 64;
        if (kv0 <= qr0 + 15) {
            const __half* Ks = smh + KOFF[buf];
            const __half* Vs = smh + VOFF[buf];

            // ---- S = Q K^T ----
            float s[8][4];
#pragma unroll
            for (int t = 0; t < 8; t++)
#pragma unroll
                for (int v = 0; v < 4; v++) s[t][v] = 0.0f;

#pragma unroll
            for (int ks = 0; ks < 8; ks++) {
#pragma unroll
                for (int t = 0; t < 8; t++) {
                    uint2 bb = *(const uint2*)(Ks + (8 * t + gid) * 144 + 16 * ks + 4 * tig);
                    mma16(s[t], qa[ks], bb.x, bb.y);
                }
            }

            // ---- P = exp(scale*S), causal mask, row sums ----
            const bool domask = (kv0 + 63 > qr0);
#pragma unroll
            for (int t = 0; t < 8; t++) {
                const int col = kv0 + 8 * t + 2 * tig;
                float p0 = __expf(s[t][0] * SCALE);
                float p1 = __expf(s[t][1] * SCALE);
                float p2 = __expf(s[t][2] * SCALE);
                float p3 = __expf(s[t][3] * SCALE);
                if (domask) {
                    const int r0 = qr0 + gid, r1 = r0 + 8;
                    if (col > r0)     p0 = 0.0f;
                    if (col + 1 > r0) p1 = 0.0f;
                    if (col > r1)     p2 = 0.0f;
                    if (col + 1 > r1) p3 = 0.0f;
                }
                l0 += p0 + p1;
                l1 += p2 + p3;
                s[t][0] = p0; s[t][1] = p1; s[t][2] = p2; s[t][3] = p3;
            }

            // ---- O += P V : A frags pack directly from accumulators ----
#pragma unroll
            for (int ks = 0; ks < 4; ks++) {
                uint32_t a[4];
                a[0] = packh2(s[2 * ks][0],     s[2 * ks][1]);
                a[1] = packh2(s[2 * ks][2],     s[2 * ks][3]);
                a[2] = packh2(s[2 * ks + 1][0], s[2 * ks + 1][1]);
                a[3] = packh2(s[2 * ks + 1][2], s[2 * ks + 1][3]);
#pragma unroll
                for (int t = 0; t < 16; t++) {
                    uint2 bb = *(const uint2*)(Vs + (8 * t + gid) * 80 + 16 * ks + 4 * tig);
                    mma16(o[t], a, bb.x, bb.y);
                }
            }
        }
        __syncthreads();
    }

    // quad-reduce row sums
#pragma unroll
    for (int off = 1; off < 4; off <<= 1) {
        l0 += __shfl_xor_sync(0xffffffffu, l0, off);
        l1 += __shfl_xor_sync(0xffffffffu, l1, off);
    }

    const int row0 = qt * 128 + 16 * w + gid;
    if (nch == 1) {
        const float i0 = 1.0f / l0, i1 = 1.0f / l1;
#pragma unroll
        for (int t = 0; t < 16; t++) {
            int h = 8 * t + 2 * tig;
            *(float2*)&out[((size_t)b * SEQ + row0) * HD + h] =
                make_float2(o[t][0] * i0, o[t][1] * i0);
            *(float2*)&out[((size_t)b * SEQ + row0 + 8) * HD + h] =
                make_float2(o[t][2] * i1, o[t][3] * i1);
        }
    } else {
        float* Op = g_Opart + (size_t)ch * BATCH * SEQ * HD;
#pragma unroll
        for (int t = 0; t < 16; t++) {
            int h = 8 * t + 2 * tig;
            *(float2*)&Op[((size_t)b * SEQ + row0) * HD + h]     = make_float2(o[t][0], o[t][1]);
            *(float2*)&Op[((size_t)b * SEQ + row0 + 8) * HD + h] = make_float2(o[t][2], o[t][3]);
        }
        if (tig == 0) {
            g_lpart[ch * BATCH * SEQ + b * SEQ + row0]     = l0;
            g_lpart[ch * BATCH * SEQ + b * SEQ + row0 + 8] = l1;
        }
        __threadfence();
        __syncthreads();
        __shared__ int s_last;
        if (tid == 0) {
            int old = atomicAdd(&g_cnt[b * 16 + qt], 1);
            s_last = (old == nch - 1) ? 1 : 0;
        }
        __syncthreads();
        if (s_last) {
            __threadfence();
#pragma unroll 4
            for (int u = 0; u < 16; u++) {
                int flat = u * 256 + tid;
                int c4 = flat & 31, rl = flat >> 5;
                size_t row = (size_t)b * SEQ + qt * 128 + rl;
                float l = 0.0f;
                float4 o4 = make_float4(0.f, 0.f, 0.f, 0.f);
                for (int c = 0; c < nch; c++) {
                    l += g_lpart[c * BATCH * SEQ + row];
                    float4 v = *(const float4*)&g_Opart[(size_t)c * BATCH * SEQ * HD + row * HD + c4 * 4];
                    o4.x += v.x; o4.y += v.y; o4.z += v.z; o4.w += v.w;
                }
                float inv = 1.0f / l;
                *(float4*)&out[row * HD + c4 * 4] =
                    make_float4(o4.x * inv, o4.y * inv, o4.z * inv, o4.w * inv);
            }
        }
    }
}

// ---------------------------------------------------------------------------
extern "C" void kernel_launch(void* const* d_in, const int* in_sizes, int n_in,
                              void* d_out, int out_size)
{
    const float* x  = (const float*)d_in[0];
    const float* Wk = (const float*)d_in[1];
    // d_in[2] = W_query: intentionally unused (reference uses W_key for q too)
    const float* Wv = (const float*)d_in[3];
    float* out = (float*)d_out;

    cudaFuncSetAttribute(proj_kernel, cudaFuncAttributeMaxDynamicSharedMemorySize, PJ_SMEM);
    cudaFuncSetAttribute(attn_kernel, cudaFuncAttributeMaxDynamicSharedMemorySize, AT_SMEM);

    transpose_w<<<dim3(8, 32), dim3(32, 8)>>>(Wk, Wv);
    proj_kernel<<<dim3(64, 2), 256, PJ_SMEM>>>(x);
    attn_kernel<<<dim3(72, 8), 256, AT_SMEM>>>(out);
}

// round 7
// speedup vs baseline: 9.3043x; 1.0392x over previous
#include <cuda_runtime.h>
#include <cuda_fp16.h>
#include <cstdint>

#define BATCH 8
#define SEQ   2048
#define EMB   1024
#define HD    128

// ---------------- scratch (allocation-free rule) ----------------
__device__ __half g_Kh [BATCH * SEQ * HD];       // K = x@Wk, fp16, h interleaved-16
__device__ __half g_Vth[BATCH * HD * SEQ];       // V^T [b][h][t], fp16, t interleaved-16
__device__ __half g_Wh [2 * HD * EMB];           // [Wk^T;Wv^T] [n=256][c=1024], c interleaved-16
__device__ float  g_Opart[8 * BATCH * SEQ * HD]; // per-chunk unnormalized O
__device__ float  g_lpart[8 * BATCH * SEQ];      // per-chunk row sums
__device__ int    g_cnt[BATCH * 16];             // per (b, qt) finished-chunk counters

// Work items (per batch): (qt, ch). chunk ch covers kv128 tiles [2ch, min(2ch+2, qt+1)).
__constant__ unsigned char ITEM_QT[72] = {
    15,15,15,15,15,15,15,15, 14,14,14,14,14,14,14, 13,13,13,13,13,13,13,
    12,12,12,12,12,12, 11,11,11,11,11,11, 10,10,10,10,10, 9,9,9,9,9,
    8,8,8,8, 7,7,7,7, 6,6,6, 5,5,5, 4,4, 3,3, 2, 1,
    14,12,10,8,6,4,2,0 };
__constant__ unsigned char ITEM_CH[72] = {
    0,1,2,3,4,5,6,7, 0,1,2,3,4,5,6, 0,1,2,3,4,5,6,
    0,1,2,3,4,5, 0,1,2,3,4,5, 0,1,2,3,4, 0,1,2,3,4,
    0,1,2,3, 0,1,2,3, 0,1,2, 0,1,2, 0,1, 0,1, 0, 0,
    7,6,5,4,3,2,1,0 };

// ---------------- helpers ----------------
__device__ __forceinline__ void cp16(uint32_t s, const void* g) {
    asm volatile("cp.async.cg.shared.global [%0], [%1], 16;" :: "r"(s), "l"(g));
}
#define CP_COMMIT() asm volatile("cp.async.commit_group;" ::: "memory")
template <int N>
__device__ __forceinline__ void cp_wait() {
    asm volatile("cp.async.wait_group %0;" :: "n"(N) : "memory");
}
__device__ __forceinline__ uint32_t packh2(float lo, float hi) {
    uint32_t d;
    asm("cvt.rn.f16x2.f32 %0, %1, %2;" : "=r"(d) : "f"(hi), "f"(lo));
    return d;
}
__device__ __forceinline__ void mma16(float* d, const uint32_t* a, uint32_t b0, uint32_t b1) {
    asm volatile("mma.sync.aligned.m16n8k16.row.col.f32.f16.f16.f32 "
        "{%0,%1,%2,%3}, {%4,%5,%6,%7}, {%8,%9}, {%0,%1,%2,%3};"
        : "+f"(d[0]), "+f"(d[1]), "+f"(d[2]), "+f"(d[3])
        : "r"(a[0]), "r"(a[1]), "r"(a[2]), "r"(a[3]), "r"(b0), "r"(b1));
}
// position of logical col c (0..15) in interleaved order [0,1,8,9,2,3,10,11,4,5,12,13,6,7,14,15]
__device__ __forceinline__ int pos16(int c) {
    return 4 * ((c & 7) >> 1) + 2 * ((c >> 3) & 1) + (c & 1);
}

// ---------------------------------------------------------------------------
// Kernel 0: W -> g_Wh (half, transposed, c interleaved-16). Also zero g_cnt.
// ---------------------------------------------------------------------------
__global__ void transpose_w(const float* __restrict__ Wk, const float* __restrict__ Wv) {
    __shared__ float t[32][33];
    if (blockIdx.x == 0 && blockIdx.y == 0) {
        int f = threadIdx.y * 32 + threadIdx.x;
        if (f < BATCH * 16) g_cnt[f] = 0;
    }
    const int n0 = blockIdx.x * 32;
    const int c0 = blockIdx.y * 32;
    const float* W = (blockIdx.x < 4) ? Wk : Wv;
    const int nb = (blockIdx.x & 3) * 32;
    for (int r = threadIdx.y; r < 32; r += 8)
        t[r][threadIdx.x] = W[(size_t)(c0 + r) * HD + nb + threadIdx.x];
    __syncthreads();
    for (int r = threadIdx.y; r < 32; r += 8) {
        int c = c0 + threadIdx.x;
        int cs = (c & ~15) + pos16(c & 15);
        g_Wh[(size_t)(n0 + r) * EMB + cs] = __float2half(t[threadIdx.x][r]);
    }
}

// ---------------------------------------------------------------------------
// Kernel 1: projection.  C[256m x 128n] = x_tile @ W  (wsel: 0 -> g_Kh, 1 -> g_Vth)
// grid (64, 2), 256 threads (8 warps). kc=64 (4 k16 steps), 2-stage cp.async.
// A tile f32 [256][72fl pad] (288B rows); B tile half [128][80h pad] (160B rows).
// ---------------------------------------------------------------------------
#define PJ_AB   73728                       // A tile bytes (256*288)
#define PJ_ST   (73728 + 20480)             // stage bytes (A + B 128*160)
#define PJ_SMEM (2 * PJ_ST)                 // 188416 bytes

__global__ __launch_bounds__(256, 1) void proj_kernel(const float* __restrict__ x) {
    extern __shared__ char smc[];
    const int tid = threadIdx.x, w = tid >> 5, lane = tid & 31;
    const int gid = lane >> 2, tig = lane & 3;
    const int m0 = blockIdx.x * 256;
    const int wsel = blockIdx.y;

    float acc[2][16][4];
#pragma unroll
    for (int i = 0; i < 2; i++)
#pragma unroll
        for (int t = 0; t < 16; t++)
#pragma unroll
            for (int v = 0; v < 4; v++) acc[i][t][v] = 0.0f;

    auto issue = [&](int st, int c) {
        char* As = smc + st * PJ_ST;
        char* Bs = As + PJ_AB;
#pragma unroll
        for (int q = 0; q < 16; q++) {    // A: 256 rows x 256B
            int f = q * 256 + tid, r = f >> 4, seg = f & 15;
            cp16((uint32_t)__cvta_generic_to_shared(As + r * 288 + seg * 16),
                 &x[(size_t)(m0 + r) * EMB + c * 64 + seg * 4]);
        }
#pragma unroll
        for (int q = 0; q < 4; q++) {     // B: 128 rows x 128B (halves)
            int f = q * 256 + tid, r = f >> 3, seg = f & 7;
            cp16((uint32_t)__cvta_generic_to_shared(Bs + r * 160 + seg * 16),
                 &g_Wh[(size_t)(wsel * 128 + r) * EMB + c * 64 + seg * 8]);
        }
    };

    issue(0, 0); CP_COMMIT();

    for (int c = 0; c < 16; c++) {
        if (c + 1 < 16) { issue((c + 1) & 1, c + 1); }
        CP_COMMIT();
        cp_wait<1>();
        __syncthreads();

        const float* As = (const float*)(smc + (c & 1) * PJ_ST);
        const __half* Bs = (const __half*)(smc + (c & 1) * PJ_ST + PJ_AB);
#pragma unroll
        for (int ks = 0; ks < 4; ks++) {
            uint32_t a[2][4];
#pragma unroll
            for (int i = 0; i < 2; i++) {
                int r = 32 * w + 16 * i + gid;
                float2 lo0 = *(const float2*)(As + r * 72 + 16 * ks + 2 * tig);
                float2 lo1 = *(const float2*)(As + (r + 8) * 72 + 16 * ks + 2 * tig);
                float2 hi0 = *(const float2*)(As + r * 72 + 16 * ks + 2 * tig + 8);
                float2 hi1 = *(const float2*)(As + (r + 8) * 72 + 16 * ks + 2 * tig + 8);
                a[i][0] = packh2(lo0.x, lo0.y);
                a[i][1] = packh2(lo1.x, lo1.y);
                a[i][2] = packh2(hi0.x, hi0.y);
                a[i][3] = packh2(hi1.x, hi1.y);
            }
#pragma unroll
            for (int t = 0; t < 16; t++) {
                uint2 bb = *(const uint2*)(Bs + (8 * t + gid) * 80 + 16 * ks + 4 * tig);
                mma16(acc[0][t], a[0], bb.x, bb.y);
                mma16(acc[1][t], a[1], bb.x, bb.y);
            }
        }
        __syncthreads();
    }

    if (wsel == 0) {
        // g_Kh: store half2, h interleaved-16: hst = 16*(t>>1) + 4*tig + 2*(t&1)
#pragma unroll
        for (int i = 0; i < 2; i++) {
            int r0 = m0 + 32 * w + 16 * i + gid;
#pragma unroll
            for (int t = 0; t < 16; t++) {
                int hst = 16 * (t >> 1) + 4 * tig + 2 * (t & 1);
                *(__half2*)&g_Kh[(size_t)r0 * HD + hst] =
                    __floats2half2_rn(acc[i][t][0], acc[i][t][1]);
                *(__half2*)&g_Kh[(size_t)(r0 + 8) * HD + hst] =
                    __floats2half2_rn(acc[i][t][2], acc[i][t][3]);
            }
        }
    } else {
        // V^T: stage in smem [h=128][t=256 pad 264], then coalesced STG.
        __half* vs = (__half*)smc;
        const int VS = 264;
#pragma unroll
        for (int i = 0; i < 2; i++) {
            int tl = 32 * w + 16 * i + gid;
            int ts0 = (tl & ~15) + pos16(gid);
            int ts1 = ts0 + 2;                     // pos16(gid+8) = pos16(gid)+2
#pragma unroll
            for (int t = 0; t < 16; t++) {
                int h0 = 8 * t + 2 * tig;
                vs[h0 * VS + ts0]       = __float2half(acc[i][t][0]);
                vs[(h0 + 1) * VS + ts0] = __float2half(acc[i][t][1]);
                vs[h0 * VS + ts1]       = __float2half(acc[i][t][2]);
                vs[(h0 + 1) * VS + ts1] = __float2half(acc[i][t][3]);
            }
        }
        __syncthreads();
        const int bb = m0 >> 11;
        const int tb = m0 & 2047;
        __half* dst = g_Vth + (size_t)bb * HD * SEQ;
        int r = tid >> 1, half128 = (tid & 1) * 128;
#pragma unroll
        for (int k = 0; k < 16; k++) {
            uint4 v = *(uint4*)&vs[r * VS + half128 + k * 8];
            *(uint4*)&dst[(size_t)r * SEQ + tb + half128 + k * 8] = v;
        }
    }
}

// ---------------------------------------------------------------------------
// Kernel 2: attention + fused combine. kv tiles of 128, double-buffered.
// Item = (qt, ch): 128 q-rows, kv128 tiles jj in [2ch, min(2ch+2, qt+1)).
// K tile [kv128][128h] stride 144h; V tile [h128][kv128] stride 144h.
// ---------------------------------------------------------------------------
#define KT0 0
#define KT1 18432                  // 128*144 halves
#define VT0 36864
#define VT1 55296
#define AT_SMEM (73728 * 2)        // 147456 bytes

__global__ __launch_bounds__(256, 1) void attn_kernel(float* __restrict__ out) {
    extern __shared__ __half smh[];
    const int tid = threadIdx.x, w = tid >> 5, lane = tid & 31;
    const int gid = lane >> 2, tig = lane & 3;
    const int b = blockIdx.y;
    const int qt = ITEM_QT[blockIdx.x];
    const int ch = ITEM_CH[blockIdx.x];
    const int jbeg = 2 * ch;
    const int jend = min(2 * ch + 2, qt + 1);
    const int nch = (qt + 2) >> 1;
    const float SCALE = 0.08838834764831845f;

    const __half* Kbh  = g_Kh  + (size_t)b * SEQ * HD;
    const __half* Vtbh = g_Vth + (size_t)b * HD * SEQ;

    const int KOFF[2] = {KT0, KT1};
    const int VOFF[2] = {VT0, VT1};

    auto stage = [&](int jj, int bsel) {
        const int tok0 = jj * 128;
        __half* Ks = smh + KOFF[bsel];
        __half* Vs = smh + VOFF[bsel];
#pragma unroll
        for (int q = 0; q < 8; q++) {          // K: 128 rows x 256B
            int f = q * 256 + tid, r = f >> 4, seg = f & 15;
            cp16((uint32_t)__cvta_generic_to_shared(Ks + r * 144 + seg * 8),
                 &Kbh[(size_t)(tok0 + r) * HD + seg * 8]);
        }
#pragma unroll
        for (int q = 0; q < 8; q++) {          // V: 128 rows x 256B
            int f = q * 256 + tid, r = f >> 4, seg = f & 15;
            cp16((uint32_t)__cvta_generic_to_shared(Vs + r * 144 + seg * 8),
                 &Vtbh[(size_t)r * SEQ + tok0 + seg * 8]);
        }
    };

    stage(jbeg, 0); CP_COMMIT();

    // Q fragments from gmem (q = key(x) source bug: read g_Kh), once per item
    const int qrow = qt * 128 + 16 * w + gid;
    const uint2* Qg0 = (const uint2*)(Kbh + (size_t)qrow * HD);
    const uint2* Qg8 = (const uint2*)(Kbh + (size_t)(qrow + 8) * HD);
    uint32_t qa[8][4];
#pragma unroll
    for (int ks = 0; ks < 8; ks++) {
        uint2 u0 = Qg0[4 * ks + tig];
        uint2 u1 = Qg8[4 * ks + tig];
        qa[ks][0] = u0.x; qa[ks][2] = u0.y;
        qa[ks][1] = u1.x; qa[ks][3] = u1.y;
    }

    float o[16][4];
#pragma unroll
    for (int t = 0; t < 16; t++)
#pragma unroll
        for (int v = 0; v < 4; v++) o[t][v] = 0.0f;
    float l0 = 0.0f, l1 = 0.0f;

    const int qr0 = qt * 128 + 16 * w;

    for (int jj = jbeg; jj < jend; jj++) {
        const int buf = (jj - jbeg) & 1;
        if (jj + 1 < jend) stage(jj + 1, buf ^ 1);
        CP_COMMIT();
        cp_wait<1>();
        __syncthreads();

        const int kv0 = jj * 128;
        if (kv0 <= qr0 + 15) {
            const __half* Ks = smh + KOFF[buf];
            const __half* Vs = smh + VOFF[buf];

            // ---- S = Q K^T  (16 q-rows x 128 kv) ----
            float s[16][4];
#pragma unroll
            for (int t = 0; t < 16; t++)
#pragma unroll
                for (int v = 0; v < 4; v++) s[t][v] = 0.0f;

#pragma unroll
            for (int ks = 0; ks < 8; ks++) {
#pragma unroll
                for (int t = 0; t < 16; t++) {
                    uint2 bb = *(const uint2*)(Ks + (8 * t + gid) * 144 + 16 * ks + 4 * tig);
                    mma16(s[t], qa[ks], bb.x, bb.y);
                }
            }

            // ---- P = exp(scale*S), causal mask, row sums ----
            const bool domask = (kv0 + 127 > qr0);
#pragma unroll
            for (int t = 0; t < 16; t++) {
                const int col = kv0 + 8 * t + 2 * tig;
                float p0 = __expf(s[t][0] * SCALE);
                float p1 = __expf(s[t][1] * SCALE);
                float p2 = __expf(s[t][2] * SCALE);
                float p3 = __expf(s[t][3] * SCALE);
                if (domask) {
                    const int r0 = qr0 + gid, r1 = r0 + 8;
                    if (col > r0)     p0 = 0.0f;
                    if (col + 1 > r0) p1 = 0.0f;
                    if (col > r1)     p2 = 0.0f;
                    if (col + 1 > r1) p3 = 0.0f;
                }
                l0 += p0 + p1;
                l1 += p2 + p3;
                s[t][0] = p0; s[t][1] = p1; s[t][2] = p2; s[t][3] = p3;
            }

            // ---- O += P V : A frags pack directly from accumulators ----
#pragma unroll
            for (int ks = 0; ks < 8; ks++) {
                uint32_t a[4];
                a[0] = packh2(s[2 * ks][0],     s[2 * ks][1]);
                a[1] = packh2(s[2 * ks][2],     s[2 * ks][3]);
                a[2] = packh2(s[2 * ks + 1][0], s[2 * ks + 1][1]);
                a[3] = packh2(s[2 * ks + 1][2], s[2 * ks + 1][3]);
#pragma unroll
                for (int t = 0; t < 16; t++) {
                    uint2 bb = *(const uint2*)(Vs + (8 * t + gid) * 144 + 16 * ks + 4 * tig);
                    mma16(o[t], a, bb.x, bb.y);
                }
            }
        }
        __syncthreads();
    }

    // quad-reduce row sums
#pragma unroll
    for (int off = 1; off < 4; off <<= 1) {
        l0 += __shfl_xor_sync(0xffffffffu, l0, off);
        l1 += __shfl_xor_sync(0xffffffffu, l1, off);
    }

    const int row0 = qt * 128 + 16 * w + gid;
    if (nch == 1) {
        const float i0 = 1.0f / l0, i1 = 1.0f / l1;
#pragma unroll
        for (int t = 0; t < 16; t++) {
            int h = 8 * t + 2 * tig;
            *(float2*)&out[((size_t)b * SEQ + row0) * HD + h] =
                make_float2(o[t][0] * i0, o[t][1] * i0);
            *(float2*)&out[((size_t)b * SEQ + row0 + 8) * HD + h] =
                make_float2(o[t][2] * i1, o[t][3] * i1);
        }
    } else {
        float* Op = g_Opart + (size_t)ch * BATCH * SEQ * HD;
#pragma unroll
        for (int t = 0; t < 16; t++) {
            int h = 8 * t + 2 * tig;
            *(float2*)&Op[((size_t)b * SEQ + row0) * HD + h]     = make_float2(o[t][0], o[t][1]);
            *(float2*)&Op[((size_t)b * SEQ + row0 + 8) * HD + h] = make_float2(o[t][2], o[t][3]);
        }
        if (tig == 0) {
            g_lpart[ch * BATCH * SEQ + b * SEQ + row0]     = l0;
            g_lpart[ch * BATCH * SEQ + b * SEQ + row0 + 8] = l1;
        }
        __threadfence();
        __syncthreads();
        __shared__ int s_last;
        if (tid == 0) {
            int old = atomicAdd(&g_cnt[b * 16 + qt], 1);
            s_last = (old == nch - 1) ? 1 : 0;
        }
        __syncthreads();
        if (s_last) {
            __threadfence();
#pragma unroll 4
            for (int u = 0; u < 16; u++) {
                int flat = u * 256 + tid;
                int c4 = flat & 31, rl = flat >> 5;
                size_t row = (size_t)b * SEQ + qt * 128 + rl;
                float l = 0.0f;
                float4 o4 = make_float4(0.f, 0.f, 0.f, 0.f);
                for (int c = 0; c < nch; c++) {
                    l += g_lpart[c * BATCH * SEQ + row];
                    float4 v = *(const float4*)&g_Opart[(size_t)c * BATCH * SEQ * HD + row * HD + c4 * 4];
                    o4.x += v.x; o4.y += v.y; o4.z += v.z; o4.w += v.w;
                }
                float inv = 1.0f / l;
                *(float4*)&out[row * HD + c4 * 4] =
                    make_float4(o4.x * inv, o4.y * inv, o4.z * inv, o4.w * inv);
            }
        }
    }
}

// ---------------------------------------------------------------------------
extern "C" void kernel_launch(void* const* d_in, const int* in_sizes, int n_in,
                              void* d_out, int out_size)
{
    const float* x  = (const float*)d_in[0];
    const float* Wk = (const float*)d_in[1];
    // d_in[2] = W_query: intentionally unused (reference uses W_key for q too)
    const float* Wv = (const float*)d_in[3];
    float* out = (float*)d_out;

    cudaFuncSetAttribute(proj_kernel, cudaFuncAttributeMaxDynamicSharedMemorySize, PJ_SMEM);
    cudaFuncSetAttribute(attn_kernel, cudaFuncAttributeMaxDynamicSharedMemorySize, AT_SMEM);

    transpose_w<<<dim3(8, 32), dim3(32, 8)>>>(Wk, Wv);
    proj_kernel<<<dim3(64, 2), 256, PJ_SMEM>>>(x);
    attn_kernel<<<dim3(72, 8), 256, AT_SMEM>>>(out);
}